// round 11
// baseline (speedup 1.0000x reference)
#include <cuda_runtime.h>
#include <cuda_bf16.h>
#include <cstdint>
#include <math.h>

// Problem constants
#define PLANE   (2048*2048)       // 4,194,304 pixels per channel plane
#define NBINS   4913              // 17^3 distinct compact keys (289a+17b+c)
#define NFEAT   20

#define NBLOCKS  148
#define NTHREADS 1024

// Reduction tail: last RBLK ticket-holders each reduce BPR bins.
#define RBLK 16
#define BPR  ((NBINS + RBLK - 1) / RBLK)     // 308 (16*308 = 4928 >= 4913)

#define MODE_INT8   0
#define MODE_INT32  1
#define MODE_FP32   2
#define MODE_BF16   3

// Staging work partition: 4913 bins x 5 int4 chunks = 24565 chunk-pairs
#define STAGE_TOTAL (NBINS * 5)
#define STAGE_PER_B ((STAGE_TOTAL + NBLOCKS - 1) / NBLOCKS)   // 166

// ---------------------------------------------------------------------------
// Global scratch. CUDA zeroes __device__ globals at module load. Invariant
// across launches / graph replays: g_hist, g_accum, g_tick1, g_tick2 are
// ZERO on entry — the final block re-zeroes everything consumed. g_stage is
// fully overwritten every launch from constant inputs. Deterministic:
// integer sums, order-independent; bin-slice partition fixed by rank.
// ---------------------------------------------------------------------------
__device__ unsigned int g_hist[2 * NBINS];   // [msb bins | lsb bins]
__device__ int          g_accum[NFEAT];
__device__ unsigned int g_tick1;             // flush-done counter
__device__ unsigned int g_tick2;             // reduction-done counter
// Compact, int32-normalized LUT rows: bin j -> 10 int4 = {msb[20] | lsb[20]}
__device__ int4         g_stage[NBINS * 10]; // 786 KB

// Scalar fetch for non-int32 upcast modes (fallback path only).
__device__ __forceinline__ int fetch_lut(const void* __restrict__ tab, int mode, long long e)
{
    switch (mode) {
        case MODE_FP32:  return (int)((const float*)tab)[e];
        case MODE_BF16:  return (int)__bfloat162float(((const __nv_bfloat16*)tab)[e]);
        default:         return (int)((const signed char*)tab)[e];
    }
}

// ---------------------------------------------------------------------------
// Single fused kernel.
// Phase A (all blocks): warp-0 LUT staging (hidden) + shared-ATOMS histogram
//   + flush to g_hist + fence + ticket. Early ticket-holders EXIT.
// Phase B (last RBLK finishers): contention-free poll (volatile load +
//   nanosleep — NOT atomics; R5's fused attempt died on same-address atomic
//   polling), then thread-per-bin reduction of a fixed slice, REDUX sums,
//   one global atomic per feature, final ticket -> quantize + write + reset.
// ---------------------------------------------------------------------------
__global__ void __launch_bounds__(NTHREADS, 1)
fused_kernel(const float* __restrict__ x_in, const float* __restrict__ x_s,
             const void* __restrict__ msb, const void* __restrict__ lsb,
             float* __restrict__ out)
{
    __shared__ unsigned int hm[NBINS];
    __shared__ unsigned int hl[NBINS];

    const int tid = threadIdx.x;
    for (int k = tid; k < NBINS; k += NTHREADS) { hm[k] = 0u; hl[k] = 0u; }
    __syncthreads();

    // --- warp 0: dtype sniff + this block's slice of LUT staging ---
    if (tid < 32) {
        const int lane = tid;
        const int* w = (const int*)msb;
        int v[8];
        #pragma unroll
        for (int s = 0; s < 8; s++) v[s] = w[lane + 32 * s];

        bool small = true, flt = true, bfl = true;
        #pragma unroll
        for (int s = 0; s < 8; s++) {
            int x = v[s];
            if (x < -32 || x > 31) small = false;
            float f = __int_as_float(x);
            if (!(isfinite(f) && f == truncf(f) && fabsf(f) <= 32.f)) flt = false;
            unsigned u = (unsigned)x;
            float h0 = __bfloat162float(__ushort_as_bfloat16((unsigned short)(u & 0xFFFFu)));
            float h1 = __bfloat162float(__ushort_as_bfloat16((unsigned short)(u >> 16)));
            if (!(isfinite(h0) && h0 == truncf(h0) && fabsf(h0) <= 32.f &&
                  isfinite(h1) && h1 == truncf(h1) && fabsf(h1) <= 32.f)) bfl = false;
        }
        int mode;
        if      (__all_sync(0xffffffffu, small)) mode = MODE_INT32;
        else if (__all_sync(0xffffffffu, flt))   mode = MODE_FP32;
        else if (__all_sync(0xffffffffu, bfl))   mode = MODE_BF16;
        else                                     mode = MODE_INT8;

        const int base = blockIdx.x * STAGE_PER_B;
        int end = base + STAGE_PER_B; if (end > STAGE_TOTAL) end = STAGE_TOTAL;
        if (mode == MODE_INT32) {
            const int4* m4 = (const int4*)msb;
            const int4* l4 = (const int4*)lsb;
            for (int t = base + lane; t < end; t += 32) {
                const int j = t / 5, q = t - 5 * j;
                g_stage[j * 10 + q]     = m4[80L * j + q];
                g_stage[j * 10 + 5 + q] = l4[80L * j + q];
            }
        } else {
            for (int t = base + lane; t < end; t += 32) {
                const int j = t / 5, q = t - 5 * j;
                const long long e = 320LL * j + 4LL * q;
                int4 vm, vl;
                vm.x = fetch_lut(msb, mode, e + 0); vm.y = fetch_lut(msb, mode, e + 1);
                vm.z = fetch_lut(msb, mode, e + 2); vm.w = fetch_lut(msb, mode, e + 3);
                vl.x = fetch_lut(lsb, mode, e + 0); vl.y = fetch_lut(lsb, mode, e + 1);
                vl.z = fetch_lut(lsb, mode, e + 2); vl.w = fetch_lut(lsb, mode, e + 3);
                g_stage[j * 10 + q]     = vm;
                g_stage[j * 10 + 5 + q] = vl;
            }
        }
    }

    // ---------------- Phase A: joint histogram ----------------
    {
        const float4* __restrict__ a0 = (const float4*)(x_in);
        const float4* __restrict__ a1 = (const float4*)(x_in + PLANE);
        const float4* __restrict__ a2 = (const float4*)(x_in + 2 * PLANE);
        const float4* __restrict__ b0 = (const float4*)(x_s);
        const float4* __restrict__ b1 = (const float4*)(x_s + PLANE);
        const float4* __restrict__ b2 = (const float4*)(x_s + 2 * PLANE);

        const int NP     = PLANE / 8;                // pairs of float4 positions
        const int stride = NBLOCKS * NTHREADS;

        for (int p = blockIdx.x * NTHREADS + tid; p < NP; p += stride) {
            const int i0 = 2 * p, i1 = 2 * p + 1;
            // 12 independent streaming loads in flight per thread.
            float4 va0 = __ldcs(&a0[i0]); float4 va1 = __ldcs(&a0[i1]);
            float4 vb0 = __ldcs(&a1[i0]); float4 vb1 = __ldcs(&a1[i1]);
            float4 vc0 = __ldcs(&a2[i0]); float4 vc1 = __ldcs(&a2[i1]);
            float4 wa0 = __ldcs(&b0[i0]); float4 wa1 = __ldcs(&b0[i1]);
            float4 wb0 = __ldcs(&b1[i0]); float4 wb1 = __ldcs(&b1[i1]);
            float4 wc0 = __ldcs(&b2[i0]); float4 wc1 = __ldcs(&b2[i1]);

            // key = 289*a + 17*b + c  (exact in fp32: max 4912 < 2^24)
            atomicAdd(&hm[(int)fmaf(289.f, va0.x, fmaf(17.f, vb0.x, vc0.x))], 1u);
            atomicAdd(&hm[(int)fmaf(289.f, va0.y, fmaf(17.f, vb0.y, vc0.y))], 1u);
            atomicAdd(&hm[(int)fmaf(289.f, va0.z, fmaf(17.f, vb0.z, vc0.z))], 1u);
            atomicAdd(&hm[(int)fmaf(289.f, va0.w, fmaf(17.f, vb0.w, vc0.w))], 1u);
            atomicAdd(&hm[(int)fmaf(289.f, va1.x, fmaf(17.f, vb1.x, vc1.x))], 1u);
            atomicAdd(&hm[(int)fmaf(289.f, va1.y, fmaf(17.f, vb1.y, vc1.y))], 1u);
            atomicAdd(&hm[(int)fmaf(289.f, va1.z, fmaf(17.f, vb1.z, vc1.z))], 1u);
            atomicAdd(&hm[(int)fmaf(289.f, va1.w, fmaf(17.f, vb1.w, vc1.w))], 1u);

            atomicAdd(&hl[(int)fmaf(289.f, wa0.x, fmaf(17.f, wb0.x, wc0.x))], 1u);
            atomicAdd(&hl[(int)fmaf(289.f, wa0.y, fmaf(17.f, wb0.y, wc0.y))], 1u);
            atomicAdd(&hl[(int)fmaf(289.f, wa0.z, fmaf(17.f, wb0.z, wc0.z))], 1u);
            atomicAdd(&hl[(int)fmaf(289.f, wa0.w, fmaf(17.f, wb0.w, wc0.w))], 1u);
            atomicAdd(&hl[(int)fmaf(289.f, wa1.x, fmaf(17.f, wb1.x, wc1.x))], 1u);
            atomicAdd(&hl[(int)fmaf(289.f, wa1.y, fmaf(17.f, wb1.y, wc1.y))], 1u);
            atomicAdd(&hl[(int)fmaf(289.f, wa1.z, fmaf(17.f, wb1.z, wc1.z))], 1u);
            atomicAdd(&hl[(int)fmaf(289.f, wa1.w, fmaf(17.f, wb1.w, wc1.w))], 1u);
        }
    }
    __syncthreads();

    // Flush into single global histogram (REDG, spread addresses).
    for (int k = tid; k < NBINS; k += NTHREADS) {
        unsigned int vm = hm[k], vl = hl[k];
        if (vm) atomicAdd(&g_hist[k], vm);
        if (vl) atomicAdd(&g_hist[NBINS + k], vl);
    }
    __threadfence();   // order staging stores + flush before the ticket
    __syncthreads();

    // ---------------- Ticket: early finishers exit ----------------
    __shared__ int s_rank;
    if (tid == 0) {
        unsigned int t = atomicAdd(&g_tick1, 1u);
        s_rank = (int)t - (NBLOCKS - RBLK);     // >=0 for the last RBLK finishers
    }
    __syncthreads();
    const int rank = s_rank;
    if (rank < 0) return;

    // ---------------- Phase B: tail reduction (last RBLK blocks) ----------------
    // Contention-free wait: volatile plain load (L2 read, no atomic-ALU lock).
    if (tid == 0) {
        volatile unsigned int* p = &g_tick1;
        while (*p < (unsigned)NBLOCKS) __nanosleep(64);
    }
    __syncthreads();
    __threadfence();   // acquire: all blocks' flushes + staging now visible

    __shared__ int s_part[NTHREADS / 32][NFEAT];
    __shared__ int s_last;
    const int wid  = tid >> 5;
    const int lane = tid & 31;

    const int jbeg = rank * BPR;
    const int j    = jbeg + tid;                 // one thread per bin (tid < BPR)
    const bool active = (tid < BPR) && (j < NBINS);

    int cm = 0, cl = 0;
    int4 c[10];
    if (active) {
        cm = (int)__ldcg(&g_hist[j]);
        cl = (int)__ldcg(&g_hist[NBINS + j]);
        const int4* row = &g_stage[j * 10];
        #pragma unroll
        for (int q = 0; q < 10; q++) c[q] = __ldcg(&row[q]);  // 160B contiguous
        g_hist[j] = 0u;                                       // zero-on-consume
        g_hist[NBINS + j] = 0u;
    } else {
        #pragma unroll
        for (int q = 0; q < 10; q++) c[q] = make_int4(0, 0, 0, 0);
    }

    int vals[NFEAT];
    #pragma unroll
    for (int q = 0; q < 5; q++) {
        vals[4*q+0] = cm * c[q].x + cl * c[5+q].x;
        vals[4*q+1] = cm * c[q].y + cl * c[5+q].y;
        vals[4*q+2] = cm * c[q].z + cl * c[5+q].z;
        vals[4*q+3] = cm * c[q].w + cl * c[5+q].w;
    }

    // Warp-level sums via REDUX; lane f keeps feature f's warp sum.
    int mine = 0;
    #pragma unroll
    for (int f = 0; f < NFEAT; f++) {
        int s = __reduce_add_sync(0xffffffffu, vals[f]);
        if (lane == f) mine = s;
    }
    if (lane < NFEAT) s_part[wid][lane] = mine;
    __syncthreads();

    if (tid < NFEAT) {
        int r = 0;
        #pragma unroll
        for (int w = 0; w < NTHREADS / 32; w++) r += s_part[w][tid];
        atomicAdd(&g_accum[tid], r);
    }
    __threadfence();
    __syncthreads();

    if (tid == 0) {
        unsigned int t = atomicAdd(&g_tick2, 1u);
        s_last = (t == RBLK - 1) ? 1 : 0;
    }
    __syncthreads();

    if (s_last && tid < NFEAT) {
        // Coherent read (L2 atomic), then reset for next launch.
        int S = atomicAdd(&g_accum[tid], 0);
        g_accum[tid] = 0;
        if (tid == 0) { g_tick1 = 0u; g_tick2 = 0u; }
        // out = clip(round(mean*4)/4, -32, 31.75)
        //     = clamp(rint(S / 2^20), -128, 127) * 0.25   (exact in double)
        double q = rint((double)S / 1048576.0);
        q = fmin(fmax(q, -128.0), 127.0);
        out[tid] = (float)(q * 0.25);
    }
}

// ---------------------------------------------------------------------------
extern "C" void kernel_launch(void* const* d_in, const int* in_sizes, int n_in,
                              void* d_out, int out_size)
{
    const float* x_in = (const float*)d_in[0];
    const float* x_s  = (const float*)d_in[1];
    const void*  msb  = d_in[2];
    const void*  lsb  = d_in[3];
    float*       out  = (float*)d_out;

    fused_kernel<<<NBLOCKS, NTHREADS>>>(x_in, x_s, msb, lsb, out);
}

// round 13
// speedup vs baseline: 1.0944x; 1.0944x over previous
#include <cuda_runtime.h>
#include <cuda_bf16.h>
#include <cstdint>
#include <math.h>

// Problem constants
#define PLANE   (2048*2048)       // 4,194,304 pixels per channel plane
#define NBINS   4913              // 17^3 distinct compact keys (289a+17b+c)
#define NFEAT   20

#define K1_BLOCKS  148
#define K1_THREADS 1024

// k2: tiny blocks so they fit in the RF headroom carved out of k1
#define K2_THREADS 64
#define K2_BLOCKS  ((NBINS + K2_THREADS - 1) / K2_THREADS)   // 77

#define MODE_INT8   0
#define MODE_INT32  1
#define MODE_FP32   2
#define MODE_BF16   3

// ---------------------------------------------------------------------------
// Global scratch. CUDA zeroes __device__ globals at module load. Invariant
// across launches / graph replays: g_hist, g_accum, g_ticket are ZERO on
// entry — kernel 2 re-zeroes everything it consumes. Deterministic:
// integer sums, order-independent.
// ---------------------------------------------------------------------------
__device__ unsigned int g_hist[2 * NBINS];   // [msb bins | lsb bins]
__device__ int          g_accum[NFEAT];
__device__ unsigned int g_ticket;

// ---------------------------------------------------------------------------
// Kernel 1: joint histogram. __maxnreg__(56) (alone — nvcc forbids combining
// it with __launch_bounds__) caps the RF use at 57344/65536 regs per SM, so
// the PDL secondary's 64-thread blocks CAN be co-resident and run their
// prologue DURING this kernel. (R8's PDL failed because 64 regs x 1024
// threads = 100% RF -> secondary could never be placed.) Occupancy is
// naturally 1 block/SM (regs + 39KB smem), so no launch_bounds needed.
// ---------------------------------------------------------------------------
__global__ void __maxnreg__(56)
hist_kernel(const float* __restrict__ x_in, const float* __restrict__ x_s)
{
    __shared__ unsigned int hm[NBINS];
    __shared__ unsigned int hl[NBINS];

    const int tid = threadIdx.x;
    for (int k = tid; k < NBINS; k += K1_THREADS) { hm[k] = 0u; hl[k] = 0u; }
    __syncthreads();

    const float4* __restrict__ a0 = (const float4*)(x_in);
    const float4* __restrict__ a1 = (const float4*)(x_in + PLANE);
    const float4* __restrict__ a2 = (const float4*)(x_in + 2 * PLANE);
    const float4* __restrict__ b0 = (const float4*)(x_s);
    const float4* __restrict__ b1 = (const float4*)(x_s + PLANE);
    const float4* __restrict__ b2 = (const float4*)(x_s + 2 * PLANE);

    const int NP     = PLANE / 8;                // pairs of float4 positions
    const int stride = K1_BLOCKS * K1_THREADS;

    for (int p = blockIdx.x * K1_THREADS + tid; p < NP; p += stride) {
        const int i0 = 2 * p, i1 = 2 * p + 1;
        // 12 independent streaming loads in flight per thread.
        float4 va0 = __ldcs(&a0[i0]); float4 va1 = __ldcs(&a0[i1]);
        float4 vb0 = __ldcs(&a1[i0]); float4 vb1 = __ldcs(&a1[i1]);
        float4 vc0 = __ldcs(&a2[i0]); float4 vc1 = __ldcs(&a2[i1]);
        float4 wa0 = __ldcs(&b0[i0]); float4 wa1 = __ldcs(&b0[i1]);
        float4 wb0 = __ldcs(&b1[i0]); float4 wb1 = __ldcs(&b1[i1]);
        float4 wc0 = __ldcs(&b2[i0]); float4 wc1 = __ldcs(&b2[i1]);

        // key = 289*a + 17*b + c  (exact in fp32: max 4912 < 2^24)
        atomicAdd(&hm[(int)fmaf(289.f, va0.x, fmaf(17.f, vb0.x, vc0.x))], 1u);
        atomicAdd(&hm[(int)fmaf(289.f, va0.y, fmaf(17.f, vb0.y, vc0.y))], 1u);
        atomicAdd(&hm[(int)fmaf(289.f, va0.z, fmaf(17.f, vb0.z, vc0.z))], 1u);
        atomicAdd(&hm[(int)fmaf(289.f, va0.w, fmaf(17.f, vb0.w, vc0.w))], 1u);
        atomicAdd(&hm[(int)fmaf(289.f, va1.x, fmaf(17.f, vb1.x, vc1.x))], 1u);
        atomicAdd(&hm[(int)fmaf(289.f, va1.y, fmaf(17.f, vb1.y, vc1.y))], 1u);
        atomicAdd(&hm[(int)fmaf(289.f, va1.z, fmaf(17.f, vb1.z, vc1.z))], 1u);
        atomicAdd(&hm[(int)fmaf(289.f, va1.w, fmaf(17.f, vb1.w, vc1.w))], 1u);

        atomicAdd(&hl[(int)fmaf(289.f, wa0.x, fmaf(17.f, wb0.x, wc0.x))], 1u);
        atomicAdd(&hl[(int)fmaf(289.f, wa0.y, fmaf(17.f, wb0.y, wc0.y))], 1u);
        atomicAdd(&hl[(int)fmaf(289.f, wa0.z, fmaf(17.f, wb0.z, wc0.z))], 1u);
        atomicAdd(&hl[(int)fmaf(289.f, wa0.w, fmaf(17.f, wb0.w, wc0.w))], 1u);
        atomicAdd(&hl[(int)fmaf(289.f, wa1.x, fmaf(17.f, wb1.x, wc1.x))], 1u);
        atomicAdd(&hl[(int)fmaf(289.f, wa1.y, fmaf(17.f, wb1.y, wc1.y))], 1u);
        atomicAdd(&hl[(int)fmaf(289.f, wa1.z, fmaf(17.f, wb1.z, wc1.z))], 1u);
        atomicAdd(&hl[(int)fmaf(289.f, wa1.w, fmaf(17.f, wb1.w, wc1.w))], 1u);
    }
    __syncthreads();

    // Flush into single global histogram (REDG, spread addresses).
    for (int k = tid; k < NBINS; k += K1_THREADS) {
        unsigned int vm = hm[k], vl = hl[k];
        if (vm) atomicAdd(&g_hist[k], vm);
        if (vl) atomicAdd(&g_hist[NBINS + k], vl);
    }
    __threadfence();     // flushes visible before the PDL trigger
    __syncthreads();
    cudaTriggerProgrammaticLaunchCompletion();
}

// Scalar fetch for non-int32 upcast modes (fallback path only).
__device__ __forceinline__ int fetch_lut(const void* __restrict__ tab, int mode, long long e)
{
    switch (mode) {
        case MODE_FP32:  return (int)((const float*)tab)[e];
        case MODE_BF16:  return (int)__bfloat162float(((const __nv_bfloat16*)tab)[e]);
        default:         return (int)((const signed char*)tab)[e];
    }
}

// ---------------------------------------------------------------------------
// Kernel 2 (reduce + final), PDL secondary: 77 blocks x 64 threads placed
// ALONGSIDE k1 blocks (fits the 8192-reg headroom). Pre-sync: dtype sniff +
// all LUT loads (input-only) — fully overlapped with k1. Post-sync: counts,
// MAC, REDUX, one atomic per feature, ticket finish. State re-zeroed.
// All sums fit int32 (|S| <= 2 * 4.2M * 32 ~= 2.7e8 < 2^31).
// ---------------------------------------------------------------------------
__global__ void __launch_bounds__(K2_THREADS)
reduce_final_kernel(const void* __restrict__ msb, const void* __restrict__ lsb,
                    float* __restrict__ out)
{
    __shared__ int s_part[K2_THREADS / 32][NFEAT];
    __shared__ int s_last;
    const int tid  = threadIdx.x;
    const int wid  = tid >> 5;
    const int lane = tid & 31;

    // ---------- PRE-SYNC (overlaps kernel 1) ----------
    // dtype sniff: every warp computes the same answer (no sync needed).
    int mode;
    {
        const int* w = (const int*)msb;
        int v[8];
        #pragma unroll
        for (int s = 0; s < 8; s++) v[s] = w[lane + 32 * s];

        bool small = true, flt = true, bfl = true;
        #pragma unroll
        for (int s = 0; s < 8; s++) {
            int x = v[s];
            if (x < -32 || x > 31) small = false;
            float f = __int_as_float(x);
            if (!(isfinite(f) && f == truncf(f) && fabsf(f) <= 32.f)) flt = false;
            unsigned u = (unsigned)x;
            float h0 = __bfloat162float(__ushort_as_bfloat16((unsigned short)(u & 0xFFFFu)));
            float h1 = __bfloat162float(__ushort_as_bfloat16((unsigned short)(u >> 16)));
            if (!(isfinite(h0) && h0 == truncf(h0) && fabsf(h0) <= 32.f &&
                  isfinite(h1) && h1 == truncf(h1) && fabsf(h1) <= 32.f)) bfl = false;
        }
        if      (__all_sync(0xffffffffu, small)) mode = MODE_INT32;
        else if (__all_sync(0xffffffffu, flt))   mode = MODE_FP32;
        else if (__all_sync(0xffffffffu, bfl))   mode = MODE_BF16;
        else                                     mode = MODE_INT8;
    }

    const int j = blockIdx.x * K2_THREADS + tid;
    const bool active = (j < NBINS);

    // LUT row loads (input-only, independent of k1's writes).
    int4 c[10];
    if (active) {
        if (mode == MODE_INT32) {
            const int4* rm = (const int4*)((const int*)msb + 320L * j);
            const int4* rl = (const int4*)((const int*)lsb + 320L * j);
            #pragma unroll
            for (int q = 0; q < 5; q++) { c[q] = rm[q]; c[5 + q] = rl[q]; }
        } else {
            const long long base = 320LL * j;
            #pragma unroll
            for (int q = 0; q < 5; q++) {
                c[q].x   = fetch_lut(msb, mode, base + 4*q + 0);
                c[q].y   = fetch_lut(msb, mode, base + 4*q + 1);
                c[q].z   = fetch_lut(msb, mode, base + 4*q + 2);
                c[q].w   = fetch_lut(msb, mode, base + 4*q + 3);
                c[5+q].x = fetch_lut(lsb, mode, base + 4*q + 0);
                c[5+q].y = fetch_lut(lsb, mode, base + 4*q + 1);
                c[5+q].z = fetch_lut(lsb, mode, base + 4*q + 2);
                c[5+q].w = fetch_lut(lsb, mode, base + 4*q + 3);
            }
        }
    } else {
        #pragma unroll
        for (int q = 0; q < 10; q++) c[q] = make_int4(0, 0, 0, 0);
    }

    // ---------- SYNC: wait for kernel 1's flushed histogram ----------
    cudaGridDependencySynchronize();

    // ---------- POST-SYNC: counts, MAC, reduce, output ----------
    int cm = 0, cl = 0;
    if (active) {
        cm = (int)__ldcg(&g_hist[j]);           // L2-coherent
        cl = (int)__ldcg(&g_hist[NBINS + j]);
        g_hist[j] = 0u;                         // zero-on-consume
        g_hist[NBINS + j] = 0u;
    }

    int vals[NFEAT];
    #pragma unroll
    for (int q = 0; q < 5; q++) {
        vals[4*q+0] = cm * c[q].x + cl * c[5+q].x;
        vals[4*q+1] = cm * c[q].y + cl * c[5+q].y;
        vals[4*q+2] = cm * c[q].z + cl * c[5+q].z;
        vals[4*q+3] = cm * c[q].w + cl * c[5+q].w;
    }

    // Warp-level sums via REDUX; lane f keeps feature f's warp sum.
    int mine = 0;
    #pragma unroll
    for (int f = 0; f < NFEAT; f++) {
        int s = __reduce_add_sync(0xffffffffu, vals[f]);
        if (lane == f) mine = s;
    }
    if (lane < NFEAT) s_part[wid][lane] = mine;
    __syncthreads();

    if (tid < NFEAT) {
        int r = 0;
        #pragma unroll
        for (int w = 0; w < K2_THREADS / 32; w++) r += s_part[w][tid];
        atomicAdd(&g_accum[tid], r);
    }
    __threadfence();
    __syncthreads();

    if (tid == 0) {
        unsigned int t = atomicAdd(&g_ticket, 1u);
        s_last = (t == K2_BLOCKS - 1) ? 1 : 0;
    }
    __syncthreads();

    if (s_last && tid < NFEAT) {
        // Coherent read (L2 atomic), then reset for next launch.
        int S = atomicAdd(&g_accum[tid], 0);
        g_accum[tid] = 0;
        if (tid == 0) g_ticket = 0u;
        // out = clip(round(mean*4)/4, -32, 31.75)
        //     = clamp(rint(S / 2^20), -128, 127) * 0.25   (exact in double)
        double q = rint((double)S / 1048576.0);
        q = fmin(fmax(q, -128.0), 127.0);
        out[tid] = (float)(q * 0.25);
    }
}

// ---------------------------------------------------------------------------
extern "C" void kernel_launch(void* const* d_in, const int* in_sizes, int n_in,
                              void* d_out, int out_size)
{
    const float* x_in = (const float*)d_in[0];
    const float* x_s  = (const float*)d_in[1];
    const void*  msb  = d_in[2];
    const void*  lsb  = d_in[3];
    float*       out  = (float*)d_out;

    hist_kernel<<<K1_BLOCKS, K1_THREADS>>>(x_in, x_s);

    // PDL secondary: prologue overlaps kernel 1 (now placeable thanks to
    // k1's __maxnreg__(56) leaving 8192 regs/SM free).
    cudaLaunchConfig_t cfg = {};
    cfg.gridDim  = dim3(K2_BLOCKS, 1, 1);
    cfg.blockDim = dim3(K2_THREADS, 1, 1);
    cfg.dynamicSmemBytes = 0;
    cfg.stream = 0;
    cudaLaunchAttribute attrs[1];
    attrs[0].id = cudaLaunchAttributeProgrammaticStreamSerialization;
    attrs[0].val.programmaticStreamSerializationAllowed = 1;
    cfg.attrs = attrs;
    cfg.numAttrs = 1;
    cudaLaunchKernelEx(&cfg, reduce_final_kernel, msb, lsb, out);
}